// round 1
// baseline (speedup 1.0000x reference)
#include <cuda_runtime.h>
#include <math.h>

#define B_  2
#define S_  2048
#define D_  1024
#define H_  16
#define HD_ 64
#define M_TOT (B_*S_)   // 4096

// Scratch (device globals — no runtime allocation allowed)
__device__ float g_q[B_*H_*S_*HD_];
__device__ float g_k[B_*H_*S_*HD_];
__device__ float g_v[B_*H_*S_*HD_];
__device__ float g_attn[B_*S_*D_];

// ---------------------------------------------------------------------------
// GEMM: C = A @ W^T + bias.   A:[M,K] row-major, W:[N,K] row-major.
// 128x128 tile, BK=16, 256 threads, 8x8 per-thread register tile.
// SPLIT=1: scatter output to [B,H,S,HD] layout (for Q/K/V).
// ---------------------------------------------------------------------------
template<int SPLIT>
__global__ __launch_bounds__(256)
void gemm_bias(const float* __restrict__ A, const float* __restrict__ W,
               const float* __restrict__ bias, float* __restrict__ C)
{
    const int K = D_;
    __shared__ float As[16][128];
    __shared__ float Ws[16][128];

    const int tid = threadIdx.x;
    const int m0 = blockIdx.y * 128;
    const int n0 = blockIdx.x * 128;
    const int ar = tid >> 2;          // 0..63
    const int ac = (tid & 3) * 4;     // 0,4,8,12
    const int ty = tid >> 4;          // 0..15
    const int tx = tid & 15;          // 0..15

    float acc[8][8];
    #pragma unroll
    for (int i = 0; i < 8; i++)
        #pragma unroll
        for (int j = 0; j < 8; j++) acc[i][j] = 0.f;

    for (int k0 = 0; k0 < K; k0 += 16) {
        #pragma unroll
        for (int rr = 0; rr < 2; rr++) {
            int row = ar + rr * 64;
            float4 av = *(const float4*)&A[(size_t)(m0 + row) * K + k0 + ac];
            As[ac+0][row] = av.x; As[ac+1][row] = av.y;
            As[ac+2][row] = av.z; As[ac+3][row] = av.w;
            float4 wv = *(const float4*)&W[(size_t)(n0 + row) * K + k0 + ac];
            Ws[ac+0][row] = wv.x; Ws[ac+1][row] = wv.y;
            Ws[ac+2][row] = wv.z; Ws[ac+3][row] = wv.w;
        }
        __syncthreads();
        #pragma unroll
        for (int kk = 0; kk < 16; kk++) {
            float a[8], b[8];
            *(float4*)&a[0] = *(const float4*)&As[kk][ty*8];
            *(float4*)&a[4] = *(const float4*)&As[kk][ty*8+4];
            *(float4*)&b[0] = *(const float4*)&Ws[kk][tx*8];
            *(float4*)&b[4] = *(const float4*)&Ws[kk][tx*8+4];
            #pragma unroll
            for (int i = 0; i < 8; i++)
                #pragma unroll
                for (int j = 0; j < 8; j++)
                    acc[i][j] += a[i] * b[j];
        }
        __syncthreads();
    }

    #pragma unroll
    for (int i = 0; i < 8; i++) {
        int m = m0 + ty*8 + i;
        #pragma unroll
        for (int j4 = 0; j4 < 2; j4++) {
            int n = n0 + tx*8 + j4*4;
            float4 v;
            v.x = acc[i][j4*4+0] + bias[n+0];
            v.y = acc[i][j4*4+1] + bias[n+1];
            v.z = acc[i][j4*4+2] + bias[n+2];
            v.w = acc[i][j4*4+3] + bias[n+3];
            if (SPLIT) {
                int b  = m >> 11;          // m / S_
                int s  = m & (S_ - 1);
                int h  = n >> 6;           // n / HD_
                int hd = n & 63;
                *(float4*)&C[(size_t)(((b*H_ + h)*S_) + s) * HD_ + hd] = v;
            } else {
                *(float4*)&C[(size_t)m * D_ + n] = v;
            }
        }
    }
}

// ---------------------------------------------------------------------------
// Flash-style attention over [B,H,S,HD] Q/K/V, writes [B,S,D] output.
// Block: 64 queries for one (b,h). 256 threads: thread = (qg 0..31, c 0..7).
// Thread owns q in {qg, qg+32}; score cols j = jj*8 + c; output dims c*8..c*8+7.
// K and V share one smem buffer; probabilities staged through Ps.
// ---------------------------------------------------------------------------
#define QSTRIDE 68   // 64 + 4 pad, float4-aligned, bank-safe
#define PSTRIDE 65

__global__ __launch_bounds__(256)
void attn_kernel(const int* __restrict__ mask)
{
    extern __shared__ float sm[];
    float* Qs = sm;                       // 64*68
    float* Ks = Qs + 64*QSTRIDE;          // 64*68 (K then V)
    float* Ps = Ks + 64*QSTRIDE;          // 64*65
    int*  Msk = (int*)(Ps + 64*PSTRIDE);  // 2048

    const int tid = threadIdx.x;
    const int bh  = blockIdx.y;           // 0..B*H-1
    const int b   = bh >> 4;              // / H_
    const int h   = bh & 15;
    const int q0  = blockIdx.x * 64;
    const int qg  = tid >> 3;             // 0..31
    const int c   = tid & 7;              // 0..7

    const float* qbase = g_q + ((size_t)bh * S_ + q0) * HD_;
    const float* kbase = g_k + (size_t)bh * S_ * HD_;
    const float* vbase = g_v + (size_t)bh * S_ * HD_;

    // Load Q tile (float4, coalesced) and the mask row
    for (int i = tid; i < 64*16; i += 256) {
        int r = i >> 4, c4 = (i & 15) << 2;
        *(float4*)&Qs[r*QSTRIDE + c4] = *(const float4*)&qbase[r*64 + c4];
    }
    for (int i = tid; i < S_; i += 256) Msk[i] = mask[b*S_ + i];

    float mrow[2] = {-1e30f, -1e30f};
    float lrow[2] = {0.f, 0.f};
    float acc[2][8];
    #pragma unroll
    for (int qi = 0; qi < 2; qi++)
        #pragma unroll
        for (int dd = 0; dd < 8; dd++) acc[qi][dd] = 0.f;

    __syncthreads();

    for (int kt = 0; kt < S_/64; kt++) {
        // --- load K tile ---
        const float* ksrc = kbase + kt * 64 * 64;
        for (int i = tid; i < 64*16; i += 256) {
            int r = i >> 4, c4 = (i & 15) << 2;
            *(float4*)&Ks[r*QSTRIDE + c4] = *(const float4*)&ksrc[r*64 + c4];
        }
        __syncthreads();

        // --- scores: s[qi][jj] = Q[q] . K[jj*8+c] ---
        float s[2][8];
        #pragma unroll
        for (int qi = 0; qi < 2; qi++)
            #pragma unroll
            for (int jj = 0; jj < 8; jj++) s[qi][jj] = 0.f;

        for (int d4 = 0; d4 < 64; d4 += 4) {
            float4 qa = *(const float4*)&Qs[qg*QSTRIDE + d4];
            float4 qb = *(const float4*)&Qs[(qg+32)*QSTRIDE + d4];
            #pragma unroll
            for (int jj = 0; jj < 8; jj++) {
                float4 kv = *(const float4*)&Ks[(jj*8 + c)*QSTRIDE + d4];
                s[0][jj] += qa.x*kv.x + qa.y*kv.y + qa.z*kv.z + qa.w*kv.w;
                s[1][jj] += qb.x*kv.x + qb.y*kv.y + qb.z*kv.z + qb.w*kv.w;
            }
        }

        // --- mask + scale ---
        const int jb = kt * 64;
        #pragma unroll
        for (int jj = 0; jj < 8; jj++) {
            int j = jj*8 + c;
            bool ok = (Msk[jb + j] != 0);
            s[0][jj] = ok ? s[0][jj] * 0.125f : -1.0e9f;
            s[1][jj] = ok ? s[1][jj] * 0.125f : -1.0e9f;
        }

        // --- online softmax update ---
        float t0 = -1e30f, t1 = -1e30f;
        #pragma unroll
        for (int jj = 0; jj < 8; jj++) {
            t0 = fmaxf(t0, s[0][jj]);
            t1 = fmaxf(t1, s[1][jj]);
        }
        #pragma unroll
        for (int o = 1; o < 8; o <<= 1) {
            t0 = fmaxf(t0, __shfl_xor_sync(0xffffffffu, t0, o));
            t1 = fmaxf(t1, __shfl_xor_sync(0xffffffffu, t1, o));
        }
        float mn0 = fmaxf(mrow[0], t0), mn1 = fmaxf(mrow[1], t1);
        float cor0 = __expf(mrow[0] - mn0), cor1 = __expf(mrow[1] - mn1);
        float ps0 = 0.f, ps1 = 0.f;
        #pragma unroll
        for (int jj = 0; jj < 8; jj++) {
            int j = jj*8 + c;
            float p0 = __expf(s[0][jj] - mn0);
            float p1 = __expf(s[1][jj] - mn1);
            Ps[qg*PSTRIDE + j]       = p0;
            Ps[(qg+32)*PSTRIDE + j]  = p1;
            ps0 += p0; ps1 += p1;
        }
        #pragma unroll
        for (int o = 1; o < 8; o <<= 1) {
            ps0 += __shfl_xor_sync(0xffffffffu, ps0, o);
            ps1 += __shfl_xor_sync(0xffffffffu, ps1, o);
        }
        lrow[0] = lrow[0]*cor0 + ps0;
        lrow[1] = lrow[1]*cor1 + ps1;
        mrow[0] = mn0; mrow[1] = mn1;
        #pragma unroll
        for (int dd = 0; dd < 8; dd++) { acc[0][dd] *= cor0; acc[1][dd] *= cor1; }

        __syncthreads();   // K reads + Ps writes complete

        // --- load V tile into same buffer ---
        const float* vsrc = vbase + kt * 64 * 64;
        for (int i = tid; i < 64*16; i += 256) {
            int r = i >> 4, c4 = (i & 15) << 2;
            *(float4*)&Ks[r*QSTRIDE + c4] = *(const float4*)&vsrc[r*64 + c4];
        }
        __syncthreads();

        // --- PV accumulate: acc[qi][dd] += sum_j P[q][j] * V[j][c*8+dd] ---
        for (int j = 0; j < 64; j++) {
            float p0 = Ps[qg*PSTRIDE + j];
            float p1 = Ps[(qg+32)*PSTRIDE + j];
            float4 va = *(const float4*)&Ks[j*QSTRIDE + c*8];
            float4 vb = *(const float4*)&Ks[j*QSTRIDE + c*8 + 4];
            acc[0][0] += p0*va.x; acc[0][1] += p0*va.y;
            acc[0][2] += p0*va.z; acc[0][3] += p0*va.w;
            acc[0][4] += p0*vb.x; acc[0][5] += p0*vb.y;
            acc[0][6] += p0*vb.z; acc[0][7] += p0*vb.w;
            acc[1][0] += p1*va.x; acc[1][1] += p1*va.y;
            acc[1][2] += p1*va.z; acc[1][3] += p1*va.w;
            acc[1][4] += p1*vb.x; acc[1][5] += p1*vb.y;
            acc[1][6] += p1*vb.z; acc[1][7] += p1*vb.w;
        }
        __syncthreads();   // before next K load / Ps overwrite
    }

    // --- epilogue: normalize + write [B,S,D] layout ---
    float inv0 = 1.0f / lrow[0];
    float inv1 = 1.0f / lrow[1];
    float* outp = g_attn + ((size_t)(b*S_ + q0)) * D_ + h * HD_;
    float4 o;
    o.x = acc[0][0]*inv0; o.y = acc[0][1]*inv0; o.z = acc[0][2]*inv0; o.w = acc[0][3]*inv0;
    *(float4*)&outp[(size_t)qg * D_ + c*8]     = o;
    o.x = acc[0][4]*inv0; o.y = acc[0][5]*inv0; o.z = acc[0][6]*inv0; o.w = acc[0][7]*inv0;
    *(float4*)&outp[(size_t)qg * D_ + c*8 + 4] = o;
    o.x = acc[1][0]*inv1; o.y = acc[1][1]*inv1; o.z = acc[1][2]*inv1; o.w = acc[1][3]*inv1;
    *(float4*)&outp[(size_t)(qg+32) * D_ + c*8]     = o;
    o.x = acc[1][4]*inv1; o.y = acc[1][5]*inv1; o.z = acc[1][6]*inv1; o.w = acc[1][7]*inv1;
    *(float4*)&outp[(size_t)(qg+32) * D_ + c*8 + 4] = o;
}

// ---------------------------------------------------------------------------
extern "C" void kernel_launch(void* const* d_in, const int* in_sizes, int n_in,
                              void* d_out, int out_size)
{
    const float* xq  = (const float*)d_in[0];
    const float* xk  = (const float*)d_in[1];
    const float* xv  = (const float*)d_in[2];
    const int*   msk = (const int*)  d_in[3];
    const float* wq  = (const float*)d_in[4];
    const float* bq  = (const float*)d_in[5];
    const float* wk  = (const float*)d_in[6];
    const float* bk  = (const float*)d_in[7];
    const float* wv  = (const float*)d_in[8];
    const float* bv  = (const float*)d_in[9];
    const float* wo  = (const float*)d_in[10];
    const float* bo  = (const float*)d_in[11];

    float *qp, *kp, *vp, *ap;
    cudaGetSymbolAddress((void**)&qp, g_q);
    cudaGetSymbolAddress((void**)&kp, g_k);
    cudaGetSymbolAddress((void**)&vp, g_v);
    cudaGetSymbolAddress((void**)&ap, g_attn);

    const int attn_smem = (64*QSTRIDE*2 + 64*PSTRIDE) * (int)sizeof(float)
                        + S_ * (int)sizeof(int);
    static bool attr_set = false;
    if (!attr_set) {
        cudaFuncSetAttribute(attn_kernel,
                             cudaFuncAttributeMaxDynamicSharedMemorySize, attn_smem);
        attr_set = true;
    }

    dim3 gg(D_/128, M_TOT/128);  // (8, 32)
    gemm_bias<1><<<gg, 256>>>(xq, wq, bq, qp);
    gemm_bias<1><<<gg, 256>>>(xk, wk, bk, kp);
    gemm_bias<1><<<gg, 256>>>(xv, wv, bv, vp);

    dim3 ga(S_/64, B_*H_);       // (32, 32)
    attn_kernel<<<ga, 256, attn_smem>>>(msk);

    gemm_bias<0><<<gg, 256>>>(ap, wo, bo, (float*)d_out);
}